// round 5
// baseline (speedup 1.0000x reference)
#include <cuda_runtime.h>
#include <cuda_bf16.h>
#include <stdint.h>

#define MAXN 100000
#define MAXE 1700000
#define C 64

// Scratch (no allocs): degree, CSR, pre-scaled features, BN stats.
__device__ int   g_is64;                      // 1 if edge_index delivered as int64
__device__ int   g_deg[MAXN];                 // 1 + in-degree
__device__ int   g_off[MAXN + 1];             // CSR offsets (in-edges only)
__device__ int   g_pos[MAXN];                 // bucket cursors
__device__ int   g_blksum[128];               // per-block scan sums
__device__ int   g_blkoff[128];               // scanned block offsets
__device__ int   g_srcIdx[MAXE];              // sources grouped by dst
__device__ float g_hn[(size_t)MAXN * C];      // hn[i][c] = (x@W)[i][c] * dinv[i]
__device__ float g_stats[2 * C];              // [0..63] sum, [64..127] sumsq

// edge accessor: works for either int32 or int64 delivery
__device__ __forceinline__ int edge_at(const void* ei, long long idx) {
    if (g_is64) return (int)((const long long*)ei)[idx];
    return ((const int*)ei)[idx];
}

// 0) detect edge_index dtype: int64 data => odd int32 words (high halves) all 0
__global__ void k_detect(const int* __restrict__ ei32) {
    __shared__ int any;
    if (threadIdx.x == 0) any = 0;
    __syncthreads();
    if (ei32[2 * threadIdx.x + 1] != 0) any = 1;   // benign race
    __syncthreads();
    if (threadIdx.x == 0) g_is64 = (any == 0) ? 1 : 0;
}

// 1) init: deg = 1 (self loop), stats = 0
__global__ void k_init(int N) {
    int i = blockIdx.x * blockDim.x + threadIdx.x;
    if (i < N) g_deg[i] = 1;
    if (i < 2 * C) g_stats[i] = 0.f;
}

// 2) in-degree count
__global__ void k_deg(const void* __restrict__ ei, int E, int N) {
    int e = blockIdx.x * blockDim.x + threadIdx.x;
    if (e < E) {
        int d = edge_at(ei, (long long)E + e);     // dst row
        if ((unsigned)d < (unsigned)N) atomicAdd(&g_deg[d], 1);
    }
}

// 3a) per-block exclusive scan of in-degree (deg-1); block sums out
__global__ void k_scanA(int N) {
    int i = blockIdx.x * 1024 + threadIdx.x;
    int v = (i < N) ? (g_deg[i] - 1) : 0;
    __shared__ int warpsum[32];
    int x = v;
    #pragma unroll
    for (int o = 1; o < 32; o <<= 1) {
        int y = __shfl_up_sync(0xffffffffu, x, o);
        if ((threadIdx.x & 31) >= o) x += y;
    }
    if ((threadIdx.x & 31) == 31) warpsum[threadIdx.x >> 5] = x;
    __syncthreads();
    if (threadIdx.x < 32) {
        int y = warpsum[threadIdx.x];
        #pragma unroll
        for (int o = 1; o < 32; o <<= 1) {
            int z = __shfl_up_sync(0xffffffffu, y, o);
            if (threadIdx.x >= o) y += z;
        }
        warpsum[threadIdx.x] = y;
    }
    __syncthreads();
    int incl = x + ((threadIdx.x >= 32) ? warpsum[(threadIdx.x >> 5) - 1] : 0);
    if (i < N) g_off[i] = incl - v;                 // block-local exclusive
    if (threadIdx.x == 1023) g_blksum[blockIdx.x] = incl;
}

// 3b) scan the (<=128) block sums with one warp
__global__ void k_scanB(int nb) {
    int lane = threadIdx.x;
    int carry = 0;
    for (int base = 0; base < nb; base += 32) {
        int v = (base + lane < nb) ? g_blksum[base + lane] : 0;
        int x = v;
        #pragma unroll
        for (int o = 1; o < 32; o <<= 1) {
            int y = __shfl_up_sync(0xffffffffu, x, o);
            if (lane >= o) x += y;
        }
        if (base + lane < nb) g_blkoff[base + lane] = carry + x - v;
        carry += __shfl_sync(0xffffffffu, x, 31);
    }
}

// 3c) add block offsets; init cursors
__global__ void k_scanC(int N, int E) {
    int i = blockIdx.x * blockDim.x + threadIdx.x;
    if (i < N) {
        int o = g_off[i] + g_blkoff[i >> 10];
        g_off[i] = o;
        g_pos[i] = o;
    }
    if (i == 0) g_off[N] = E;
}

// 4) bucket edges by dst
__global__ void k_bucket(const void* __restrict__ ei, int E, int N) {
    int e = blockIdx.x * blockDim.x + threadIdx.x;
    if (e < E) {
        int s = edge_at(ei, e);
        int d = edge_at(ei, (long long)E + e);
        if ((unsigned)d < (unsigned)N && (unsigned)s < (unsigned)N) {
            int p = atomicAdd(&g_pos[d], 1);
            g_srcIdx[p] = s;
        }
    }
}

// 5) h = x @ W, pre-scaled by dinv[row]  (256 thr = 4 rows x 64 cols)
__global__ void k_h(const float* __restrict__ x, const float* __restrict__ W,
                    int N) {
    __shared__ float Ws[64 * 64];
    __shared__ float xs[4][64];
    for (int i = threadIdx.x; i < 64 * 64; i += 256) Ws[i] = W[i];
    int c  = threadIdx.x & 63;
    int rs = threadIdx.x >> 6;
    int base = blockIdx.x * 64;
    for (int r0 = 0; r0 < 64; r0 += 4) {
        int row = base + r0 + rs;
        __syncthreads();
        xs[rs][c] = (row < N) ? x[(size_t)row * C + c] : 0.f;
        __syncthreads();
        if (row < N) {
            float acc = 0.f;
            #pragma unroll
            for (int k = 0; k < 64; k++)
                acc = fmaf(xs[rs][k], Ws[k * 64 + c], acc);
            g_hn[(size_t)row * C + c] = acc * rsqrtf((float)g_deg[row]);
        }
    }
}

// 6) gather: one warp per node. out[i] = dinv[i] * (hn[i] + sum_nbr hn[s])
__global__ void k_gather(float* __restrict__ out, int N) {
    int node = blockIdx.x * (blockDim.x >> 5) + (threadIdx.x >> 5);
    if (node >= N) return;
    int lane = threadIdx.x & 31;
    const float2* hn2 = (const float2*)g_hn;
    int beg = g_off[node], end = g_off[node + 1];
    float2 acc = hn2[(size_t)node * 32 + lane];          // self term
    for (int j0 = beg; j0 < end; j0 += 32) {
        int nj = end - j0; if (nj > 32) nj = 32;
        int sj = (lane < nj) ? g_srcIdx[j0 + lane] : 0;  // coalesced
        for (int t = 0; t < nj; t++) {
            int s = __shfl_sync(0xffffffffu, sj, t);
            float2 v = hn2[(size_t)s * 32 + lane];       // 256B/warp, coalesced
            acc.x += v.x; acc.y += v.y;
        }
    }
    float dinv = rsqrtf((float)g_deg[node]);
    float2 r; r.x = acc.x * dinv; r.y = acc.y * dinv;
    ((float2*)out)[(size_t)node * 32 + lane] = r;
}

// 7) per-column sum / sumsq
__global__ void k_stats(const float* __restrict__ out, int N) {
    int c  = threadIdx.x & 63;
    int rs = threadIdx.x >> 6;
    float s = 0.f, s2 = 0.f;
    for (int row = blockIdx.x * 4 + rs; row < N; row += gridDim.x * 4) {
        float v = out[(size_t)row * C + c];
        s += v; s2 += v * v;
    }
    __shared__ float sh[256], sh2[256];
    sh[threadIdx.x] = s; sh2[threadIdx.x] = s2;
    __syncthreads();
    if (rs == 0) {
        s  = sh[c]  + sh[64 + c]  + sh[128 + c]  + sh[192 + c];
        s2 = sh2[c] + sh2[64 + c] + sh2[128 + c] + sh2[192 + c];
        atomicAdd(&g_stats[c], s);
        atomicAdd(&g_stats[64 + c], s2);
    }
}

// 8) BN + ReLU (bias cancels exactly in training-mode BN)
__global__ void k_bn(float* __restrict__ out, const float* __restrict__ gamma,
                     const float* __restrict__ beta, int N) {
    __shared__ float scale[64], shift[64];
    if (threadIdx.x < 64) {
        float n = (float)N;
        float mean = g_stats[threadIdx.x] / n;
        float var  = g_stats[64 + threadIdx.x] / n - mean * mean;
        float sc = rsqrtf(var + 1e-5f) * gamma[threadIdx.x];
        scale[threadIdx.x] = sc;
        shift[threadIdx.x] = beta[threadIdx.x] - mean * sc;
    }
    __syncthreads();
    long long i = (long long)blockIdx.x * blockDim.x + threadIdx.x;
    if (i < (long long)N * C) {
        int c = (int)(i & 63);
        out[i] = fmaxf(fmaf(out[i], scale[c], shift[c]), 0.f);
    }
}

extern "C" void kernel_launch(void* const* d_in, const int* in_sizes, int n_in,
                              void* d_out, int out_size) {
    const float* x     = (const float*)d_in[0];
    const void*  ei    = d_in[1];                 // int32 or int64; detected on device
    const float* W     = (const float*)d_in[2];
    // d_in[3] = bias (cancels exactly in training-mode BN; unused)
    const float* gamma = (const float*)d_in[4];
    const float* beta  = (const float*)d_in[5];
    float* out = (float*)d_out;

    int N = in_sizes[0] / C;
    int E = in_sizes[1] / 2;
    int nb = (N + 1023) / 1024;

    k_detect<<<1, 256>>>((const int*)ei);
    k_init<<<(N + 255) / 256, 256>>>(N);
    k_deg<<<(E + 255) / 256, 256>>>(ei, E, N);
    k_scanA<<<nb, 1024>>>(N);
    k_scanB<<<1, 32>>>(nb);
    k_scanC<<<(N + 255) / 256, 256>>>(N, E);
    k_bucket<<<(E + 255) / 256, 256>>>(ei, E, N);
    k_h<<<(N + 63) / 64, 256>>>(x, W, N);
    k_gather<<<(N + 7) / 8, 256>>>(out, N);
    k_stats<<<512, 256>>>(out, N);
    long long tot = (long long)N * C;
    k_bn<<<(unsigned)((tot + 255) / 256), 256>>>(out, gamma, beta, N);
}

// round 9
// speedup vs baseline: 1.0574x; 1.0574x over previous
#include <cuda_runtime.h>
#include <cuda_bf16.h>
#include <stdint.h>

#define MAXN 100000
#define MAXE 1700000
#define C 64

__device__ int   g_is64;
__device__ int   g_deg[MAXN];                 // 1 + in-degree
__device__ int   g_off[MAXN + 1];             // CSR offsets (in-edges only)
__device__ int   g_pos[MAXN];                 // bucket cursors
__device__ int   g_blksum[128];
__device__ int   g_blkoff[128];
__device__ int   g_srcIdx[MAXE];              // sources grouped by dst
__device__ float g_hn[(size_t)MAXN * C];      // hn[i][c] = (x@W)[i][c] * dinv[i]
__device__ float g_stats[2 * C];

// packed f32x2 helpers (sm_100+)
__device__ __forceinline__ float2 add2(float2 a, float2 b) {
    float2 r;
    asm("add.rn.f32x2 %0, %1, %2;"
        : "=l"(reinterpret_cast<unsigned long long&>(r))
        : "l"(reinterpret_cast<unsigned long long&>(a)),
          "l"(reinterpret_cast<unsigned long long&>(b)));
    return r;
}
__device__ __forceinline__ float2 ffma2(float2 a, float2 b, float2 c) {
    float2 r;
    asm("fma.rn.f32x2 %0, %1, %2, %3;"
        : "=l"(reinterpret_cast<unsigned long long&>(r))
        : "l"(reinterpret_cast<unsigned long long&>(a)),
          "l"(reinterpret_cast<unsigned long long&>(b)),
          "l"(reinterpret_cast<unsigned long long&>(c)));
    return r;
}
__device__ __forceinline__ float2 bcast2(float a) {
    float2 r;
    asm("mov.b64 %0, {%1, %1};"
        : "=l"(reinterpret_cast<unsigned long long&>(r)) : "f"(a));
    return r;
}

__device__ __forceinline__ int edge_at(const void* ei, long long idx) {
    if (g_is64) return (int)((const long long*)ei)[idx];
    return ((const int*)ei)[idx];
}

// 1) init deg/stats + dtype detection (block 0)
__global__ void k_init(const int* __restrict__ ei32, int N) {
    int i = blockIdx.x * blockDim.x + threadIdx.x;
    if (i < N) g_deg[i] = 1;
    if (i < 2 * C) g_stats[i] = 0.f;
    if (blockIdx.x == 0) {
        __shared__ int any;
        if (threadIdx.x == 0) any = 0;
        __syncthreads();
        if (ei32[2 * threadIdx.x + 1] != 0) any = 1;  // benign race
        __syncthreads();
        if (threadIdx.x == 0) g_is64 = (any == 0) ? 1 : 0;
    }
}

// 2) in-degree count
__global__ void k_deg(const void* __restrict__ ei, int E, int N) {
    int e = blockIdx.x * blockDim.x + threadIdx.x;
    if (e < E) {
        int d = edge_at(ei, (long long)E + e);
        if ((unsigned)d < (unsigned)N) atomicAdd(&g_deg[d], 1);
    }
}

// 3a) per-block exclusive scan of (deg-1)
__global__ void k_scanA(int N) {
    int i = blockIdx.x * 1024 + threadIdx.x;
    int v = (i < N) ? (g_deg[i] - 1) : 0;
    __shared__ int warpsum[32];
    int x = v;
    #pragma unroll
    for (int o = 1; o < 32; o <<= 1) {
        int y = __shfl_up_sync(0xffffffffu, x, o);
        if ((threadIdx.x & 31) >= o) x += y;
    }
    if ((threadIdx.x & 31) == 31) warpsum[threadIdx.x >> 5] = x;
    __syncthreads();
    if (threadIdx.x < 32) {
        int y = warpsum[threadIdx.x];
        #pragma unroll
        for (int o = 1; o < 32; o <<= 1) {
            int z = __shfl_up_sync(0xffffffffu, y, o);
            if (threadIdx.x >= o) y += z;
        }
        warpsum[threadIdx.x] = y;
    }
    __syncthreads();
    int incl = x + ((threadIdx.x >= 32) ? warpsum[(threadIdx.x >> 5) - 1] : 0);
    if (i < N) g_off[i] = incl - v;
    if (threadIdx.x == 1023) g_blksum[blockIdx.x] = incl;
}

// 3b) scan block sums (one warp)
__global__ void k_scanB(int nb) {
    int lane = threadIdx.x;
    int carry = 0;
    for (int base = 0; base < nb; base += 32) {
        int v = (base + lane < nb) ? g_blksum[base + lane] : 0;
        int x = v;
        #pragma unroll
        for (int o = 1; o < 32; o <<= 1) {
            int y = __shfl_up_sync(0xffffffffu, x, o);
            if (lane >= o) x += y;
        }
        if (base + lane < nb) g_blkoff[base + lane] = carry + x - v;
        carry += __shfl_sync(0xffffffffu, x, 31);
    }
}

// 3c) add block offsets; init cursors
__global__ void k_scanC(int N, int E) {
    int i = blockIdx.x * blockDim.x + threadIdx.x;
    if (i < N) {
        int o = g_off[i] + g_blkoff[i >> 10];
        g_off[i] = o;
        g_pos[i] = o;
    }
    if (i == 0) g_off[N] = E;
}

// 4) bucket edges by dst
__global__ void k_bucket(const void* __restrict__ ei, int E, int N) {
    int e = blockIdx.x * blockDim.x + threadIdx.x;
    if (e < E) {
        int s = edge_at(ei, e);
        int d = edge_at(ei, (long long)E + e);
        if ((unsigned)d < (unsigned)N && (unsigned)s < (unsigned)N) {
            int p = atomicAdd(&g_pos[d], 1);
            g_srcIdx[p] = s;
        }
    }
}

// 5) h = x @ W, scaled by dinv[row].  Register-tiled: 256 thr, 64x64 tile,
//    each thread 4 rows x 4 cols, FFMA2 packed.
__global__ void k_h(const float* __restrict__ x, const float* __restrict__ W,
                    int N) {
    __shared__ float Wsm[64 * 64];              // [k][c] row-major
    __shared__ float Xt[64 * 68];               // [k][row], stride 68 (16B-aligned)
    int tid = threadIdx.x;
    int base = blockIdx.x * 64;

    // load W (coalesced float4)
    {
        const float4* w4 = (const float4*)W;
        float4* s4 = (float4*)Wsm;
        for (int i = tid; i < 64 * 16; i += 256) s4[i] = w4[i];
    }
    // load X tile transposed: slot s covers row=s/16, cols 4*(s%16)
    for (int s = tid; s < 1024; s += 256) {
        int row = s >> 4;
        int c0 = (s & 15) * 4;
        int gr = base + row;
        float4 v = (gr < N) ? *(const float4*)&x[(size_t)gr * C + c0]
                            : make_float4(0.f, 0.f, 0.f, 0.f);
        Xt[(c0 + 0) * 68 + row] = v.x;
        Xt[(c0 + 1) * 68 + row] = v.y;
        Xt[(c0 + 2) * 68 + row] = v.z;
        Xt[(c0 + 3) * 68 + row] = v.w;
    }
    __syncthreads();

    int tx = tid & 15;         // col group
    int ty = tid >> 4;         // row group
    int c0 = tx * 4;
    int r0 = ty * 4;

    float2 acc[4][2];
    #pragma unroll
    for (int r = 0; r < 4; r++) { acc[r][0] = make_float2(0.f, 0.f);
                                  acc[r][1] = make_float2(0.f, 0.f); }
    #pragma unroll 8
    for (int k = 0; k < 64; k++) {
        float4 wb = *(const float4*)&Wsm[k * 64 + c0];
        float4 xa = *(const float4*)&Xt[k * 68 + r0];
        float2 b01 = make_float2(wb.x, wb.y);
        float2 b23 = make_float2(wb.z, wb.w);
        float2 a0 = bcast2(xa.x), a1 = bcast2(xa.y);
        float2 a2 = bcast2(xa.z), a3 = bcast2(xa.w);
        acc[0][0] = ffma2(a0, b01, acc[0][0]); acc[0][1] = ffma2(a0, b23, acc[0][1]);
        acc[1][0] = ffma2(a1, b01, acc[1][0]); acc[1][1] = ffma2(a1, b23, acc[1][1]);
        acc[2][0] = ffma2(a2, b01, acc[2][0]); acc[2][1] = ffma2(a2, b23, acc[2][1]);
        acc[3][0] = ffma2(a3, b01, acc[3][0]); acc[3][1] = ffma2(a3, b23, acc[3][1]);
    }
    #pragma unroll
    for (int r = 0; r < 4; r++) {
        int row = base + r0 + r;
        if (row < N) {
            float dinv = rsqrtf((float)g_deg[row]);
            float4 o;
            o.x = acc[r][0].x * dinv; o.y = acc[r][0].y * dinv;
            o.z = acc[r][1].x * dinv; o.w = acc[r][1].y * dinv;
            *(float4*)&g_hn[(size_t)row * C + c0] = o;
        }
    }
}

// 6) gather: one warp per node. out[i] = dinv[i] * (hn[i] + sum_nbr hn[s])
__global__ void k_gather(float* __restrict__ out, int N) {
    int node = blockIdx.x * (blockDim.x >> 5) + (threadIdx.x >> 5);
    if (node >= N) return;
    int lane = threadIdx.x & 31;
    const float2* hn2 = (const float2*)g_hn;
    int beg = g_off[node], end = g_off[node + 1];
    float2 acc = __ldg(&hn2[(size_t)node * 32 + lane]);   // self term
    for (int j0 = beg; j0 < end; j0 += 32) {
        int nj = end - j0; if (nj > 32) nj = 32;
        int sj = (lane < nj) ? __ldg(&g_srcIdx[j0 + lane]) : 0;
        int t = 0;
        for (; t + 4 <= nj; t += 4) {
            int s0 = __shfl_sync(0xffffffffu, sj, t);
            int s1 = __shfl_sync(0xffffffffu, sj, t + 1);
            int s2 = __shfl_sync(0xffffffffu, sj, t + 2);
            int s3 = __shfl_sync(0xffffffffu, sj, t + 3);
            float2 v0 = __ldg(&hn2[(size_t)s0 * 32 + lane]);
            float2 v1 = __ldg(&hn2[(size_t)s1 * 32 + lane]);
            float2 v2 = __ldg(&hn2[(size_t)s2 * 32 + lane]);
            float2 v3 = __ldg(&hn2[(size_t)s3 * 32 + lane]);
            acc = add2(acc, add2(add2(v0, v1), add2(v2, v3)));
        }
        for (; t < nj; t++) {
            int s = __shfl_sync(0xffffffffu, sj, t);
            acc = add2(acc, __ldg(&hn2[(size_t)s * 32 + lane]));
        }
    }
    float dinv = rsqrtf((float)g_deg[node]);
    float2 r; r.x = acc.x * dinv; r.y = acc.y * dinv;
    ((float2*)out)[(size_t)node * 32 + lane] = r;
}

// 7) per-column sum / sumsq
__global__ void k_stats(const float* __restrict__ out, int N) {
    int c  = threadIdx.x & 63;
    int rs = threadIdx.x >> 6;
    float s = 0.f, s2 = 0.f;
    for (int row = blockIdx.x * 4 + rs; row < N; row += gridDim.x * 4) {
        float v = out[(size_t)row * C + c];
        s += v; s2 += v * v;
    }
    __shared__ float sh[256], sh2[256];
    sh[threadIdx.x] = s; sh2[threadIdx.x] = s2;
    __syncthreads();
    if (rs == 0) {
        s  = sh[c]  + sh[64 + c]  + sh[128 + c]  + sh[192 + c];
        s2 = sh2[c] + sh2[64 + c] + sh2[128 + c] + sh2[192 + c];
        atomicAdd(&g_stats[c], s);
        atomicAdd(&g_stats[64 + c], s2);
    }
}

// 8) BN + ReLU, float4 (bias cancels exactly in training-mode BN)
__global__ void k_bn(float* __restrict__ out, const float* __restrict__ gamma,
                     const float* __restrict__ beta, int N) {
    __shared__ float scale[64], shift[64];
    if (threadIdx.x < 64) {
        float n = (float)N;
        float mean = g_stats[threadIdx.x] / n;
        float var  = g_stats[64 + threadIdx.x] / n - mean * mean;
        float sc = rsqrtf(var + 1e-5f) * gamma[threadIdx.x];
        scale[threadIdx.x] = sc;
        shift[threadIdx.x] = beta[threadIdx.x] - mean * sc;
    }
    __syncthreads();
    long long i4 = (long long)blockIdx.x * blockDim.x + threadIdx.x;
    long long tot4 = (long long)N * C / 4;
    if (i4 < tot4) {
        int c0 = (int)((i4 * 4) & 63);
        float4 v = ((const float4*)out)[i4];
        v.x = fmaxf(fmaf(v.x, scale[c0 + 0], shift[c0 + 0]), 0.f);
        v.y = fmaxf(fmaf(v.y, scale[c0 + 1], shift[c0 + 1]), 0.f);
        v.z = fmaxf(fmaf(v.z, scale[c0 + 2], shift[c0 + 2]), 0.f);
        v.w = fmaxf(fmaf(v.w, scale[c0 + 3], shift[c0 + 3]), 0.f);
        ((float4*)out)[i4] = v;
    }
}

extern "C" void kernel_launch(void* const* d_in, const int* in_sizes, int n_in,
                              void* d_out, int out_size) {
    const float* x     = (const float*)d_in[0];
    const void*  ei    = d_in[1];                 // int32 or int64; device-detected
    const float* W     = (const float*)d_in[2];
    // d_in[3] = bias (cancels exactly in training-mode BN; unused)
    const float* gamma = (const float*)d_in[4];
    const float* beta  = (const float*)d_in[5];
    float* out = (float*)d_out;

    int N = in_sizes[0] / C;
    int E = in_sizes[1] / 2;
    int nb = (N + 1023) / 1024;

    k_init<<<(N + 255) / 256, 256>>>((const int*)ei, N);
    k_deg<<<(E + 255) / 256, 256>>>(ei, E, N);
    k_scanA<<<nb, 1024>>>(N);
    k_scanB<<<1, 32>>>(nb);
    k_scanC<<<(N + 255) / 256, 256>>>(N, E);
    k_bucket<<<(E + 255) / 256, 256>>>(ei, E, N);
    k_h<<<(N + 63) / 64, 256>>>(x, W, N);
    k_gather<<<(N + 7) / 8, 256>>>(out, N);
    k_stats<<<512, 256>>>(out, N);
    long long tot4 = (long long)N * C / 4;
    k_bn<<<(unsigned)((tot4 + 255) / 256), 256>>>(out, gamma, beta, N);
}

// round 11
// speedup vs baseline: 1.3143x; 1.2429x over previous
#include <cuda_runtime.h>
#include <cuda_bf16.h>
#include <stdint.h>

#define MAXN 100000
#define MAXE 1700000
#define C 64

__device__ int   g_is64;
__device__ int   g_deg[MAXN];                 // 1 + in-degree
__device__ int   g_off[MAXN + 1];             // CSR offsets (in-edges only)
__device__ int   g_pos[MAXN];                 // bucket cursors
__device__ int   g_blksum[128];
__device__ int   g_srcIdx[MAXE];              // sources grouped by dst
__device__ float g_hn[(size_t)MAXN * C];      // hn[i][c] = (x@W)[i][c] * dinv[i]
__device__ float g_stats[2 * C];

// packed f32x2 helpers (sm_100+)
__device__ __forceinline__ float2 add2(float2 a, float2 b) {
    float2 r;
    asm("add.rn.f32x2 %0, %1, %2;"
        : "=l"(reinterpret_cast<unsigned long long&>(r))
        : "l"(reinterpret_cast<unsigned long long&>(a)),
          "l"(reinterpret_cast<unsigned long long&>(b)));
    return r;
}
__device__ __forceinline__ float2 ffma2(float2 a, float2 b, float2 c) {
    float2 r;
    asm("fma.rn.f32x2 %0, %1, %2, %3;"
        : "=l"(reinterpret_cast<unsigned long long&>(r))
        : "l"(reinterpret_cast<unsigned long long&>(a)),
          "l"(reinterpret_cast<unsigned long long&>(b)),
          "l"(reinterpret_cast<unsigned long long&>(c)));
    return r;
}
__device__ __forceinline__ float2 bcast2(float a) {
    float2 r;
    asm("mov.b64 %0, {%1, %1};"
        : "=l"(reinterpret_cast<unsigned long long&>(r)) : "f"(a));
    return r;
}

__device__ __forceinline__ int edge_at(const void* ei, long long idx) {
    if (g_is64) return (int)((const long long*)ei)[idx];
    return ((const int*)ei)[idx];
}

// 1) init deg/stats + dtype detection (block 0)
__global__ void k_init(const int* __restrict__ ei32, int N) {
    int i = blockIdx.x * blockDim.x + threadIdx.x;
    if (i < N) g_deg[i] = 1;
    if (i < 2 * C) g_stats[i] = 0.f;
    if (blockIdx.x == 0) {
        __shared__ int any;
        if (threadIdx.x == 0) any = 0;
        __syncthreads();
        if (ei32[2 * threadIdx.x + 1] != 0) any = 1;  // benign race
        __syncthreads();
        if (threadIdx.x == 0) g_is64 = (any == 0) ? 1 : 0;
    }
}

// 2) in-degree count (4 edges/thread, int4 fast path)
__global__ void k_deg(const void* __restrict__ ei, int E, int N) {
    int e0 = (blockIdx.x * blockDim.x + threadIdx.x) * 4;
    if (e0 >= E) return;
    if (!g_is64 && e0 + 4 <= E) {
        int4 d4 = *(const int4*)((const int*)ei + E + e0);
        if ((unsigned)d4.x < (unsigned)N) atomicAdd(&g_deg[d4.x], 1);
        if ((unsigned)d4.y < (unsigned)N) atomicAdd(&g_deg[d4.y], 1);
        if ((unsigned)d4.z < (unsigned)N) atomicAdd(&g_deg[d4.z], 1);
        if ((unsigned)d4.w < (unsigned)N) atomicAdd(&g_deg[d4.w], 1);
    } else {
        int eend = e0 + 4 < E ? e0 + 4 : E;
        for (int e = e0; e < eend; e++) {
            int d = edge_at(ei, (long long)E + e);
            if ((unsigned)d < (unsigned)N) atomicAdd(&g_deg[d], 1);
        }
    }
}

// 3a) per-block exclusive scan of (deg-1)
__global__ void k_scanA(int N) {
    int i = blockIdx.x * 1024 + threadIdx.x;
    int v = (i < N) ? (g_deg[i] - 1) : 0;
    __shared__ int warpsum[32];
    int x = v;
    #pragma unroll
    for (int o = 1; o < 32; o <<= 1) {
        int y = __shfl_up_sync(0xffffffffu, x, o);
        if ((threadIdx.x & 31) >= o) x += y;
    }
    if ((threadIdx.x & 31) == 31) warpsum[threadIdx.x >> 5] = x;
    __syncthreads();
    if (threadIdx.x < 32) {
        int y = warpsum[threadIdx.x];
        #pragma unroll
        for (int o = 1; o < 32; o <<= 1) {
            int z = __shfl_up_sync(0xffffffffu, y, o);
            if (threadIdx.x >= o) y += z;
        }
        warpsum[threadIdx.x] = y;
    }
    __syncthreads();
    int incl = x + ((threadIdx.x >= 32) ? warpsum[(threadIdx.x >> 5) - 1] : 0);
    if (i < N) g_off[i] = incl - v;
    if (threadIdx.x == 1023) g_blksum[blockIdx.x] = incl;
}

// 3b) add block offsets (block-sum scan done redundantly per block); init cursors
__global__ void k_scanC(int N, int E, int nb) {
    __shared__ int boff[128];
    if (threadIdx.x < 32) {
        int lane = threadIdx.x;
        int carry = 0;
        for (int base = 0; base < nb; base += 32) {
            int v = (base + lane < nb) ? g_blksum[base + lane] : 0;
            int x = v;
            #pragma unroll
            for (int o = 1; o < 32; o <<= 1) {
                int y = __shfl_up_sync(0xffffffffu, x, o);
                if (lane >= o) x += y;
            }
            if (base + lane < nb) boff[base + lane] = carry + x - v;
            carry += __shfl_sync(0xffffffffu, x, 31);
        }
    }
    __syncthreads();
    int i = blockIdx.x * blockDim.x + threadIdx.x;
    if (i < N) {
        int o = g_off[i] + boff[i >> 10];
        g_off[i] = o;
        g_pos[i] = o;
    }
    if (i == 0) g_off[N] = E;
}

// 4) bucket edges by dst (4 edges/thread, int4 fast path)
__global__ void k_bucket(const void* __restrict__ ei, int E, int N) {
    int e0 = (blockIdx.x * blockDim.x + threadIdx.x) * 4;
    if (e0 >= E) return;
    if (!g_is64 && e0 + 4 <= E) {
        const int* p = (const int*)ei;
        int4 s4 = *(const int4*)(p + e0);
        int4 d4 = *(const int4*)(p + E + e0);
        if ((unsigned)d4.x < (unsigned)N && (unsigned)s4.x < (unsigned)N)
            g_srcIdx[atomicAdd(&g_pos[d4.x], 1)] = s4.x;
        if ((unsigned)d4.y < (unsigned)N && (unsigned)s4.y < (unsigned)N)
            g_srcIdx[atomicAdd(&g_pos[d4.y], 1)] = s4.y;
        if ((unsigned)d4.z < (unsigned)N && (unsigned)s4.z < (unsigned)N)
            g_srcIdx[atomicAdd(&g_pos[d4.z], 1)] = s4.z;
        if ((unsigned)d4.w < (unsigned)N && (unsigned)s4.w < (unsigned)N)
            g_srcIdx[atomicAdd(&g_pos[d4.w], 1)] = s4.w;
    } else {
        int eend = e0 + 4 < E ? e0 + 4 : E;
        for (int e = e0; e < eend; e++) {
            int s = edge_at(ei, e);
            int d = edge_at(ei, (long long)E + e);
            if ((unsigned)d < (unsigned)N && (unsigned)s < (unsigned)N)
                g_srcIdx[atomicAdd(&g_pos[d], 1)] = s;
        }
    }
}

// 5) h = x @ W, scaled by dinv[row].  Register-tiled, FFMA2 packed.
__global__ void k_h(const float* __restrict__ x, const float* __restrict__ W,
                    int N) {
    __shared__ float Wsm[64 * 64];
    __shared__ float Xt[64 * 68];
    int tid = threadIdx.x;
    int base = blockIdx.x * 64;
    {
        const float4* w4 = (const float4*)W;
        float4* s4 = (float4*)Wsm;
        for (int i = tid; i < 64 * 16; i += 256) s4[i] = w4[i];
    }
    for (int s = tid; s < 1024; s += 256) {
        int row = s >> 4;
        int c0 = (s & 15) * 4;
        int gr = base + row;
        float4 v = (gr < N) ? *(const float4*)&x[(size_t)gr * C + c0]
                            : make_float4(0.f, 0.f, 0.f, 0.f);
        Xt[(c0 + 0) * 68 + row] = v.x;
        Xt[(c0 + 1) * 68 + row] = v.y;
        Xt[(c0 + 2) * 68 + row] = v.z;
        Xt[(c0 + 3) * 68 + row] = v.w;
    }
    __syncthreads();

    int tx = tid & 15, ty = tid >> 4;
    int c0 = tx * 4, r0 = ty * 4;
    float2 acc[4][2];
    #pragma unroll
    for (int r = 0; r < 4; r++) { acc[r][0] = make_float2(0.f, 0.f);
                                  acc[r][1] = make_float2(0.f, 0.f); }
    #pragma unroll 8
    for (int k = 0; k < 64; k++) {
        float4 wb = *(const float4*)&Wsm[k * 64 + c0];
        float4 xa = *(const float4*)&Xt[k * 68 + r0];
        float2 b01 = make_float2(wb.x, wb.y);
        float2 b23 = make_float2(wb.z, wb.w);
        float2 a0 = bcast2(xa.x), a1 = bcast2(xa.y);
        float2 a2 = bcast2(xa.z), a3 = bcast2(xa.w);
        acc[0][0] = ffma2(a0, b01, acc[0][0]); acc[0][1] = ffma2(a0, b23, acc[0][1]);
        acc[1][0] = ffma2(a1, b01, acc[1][0]); acc[1][1] = ffma2(a1, b23, acc[1][1]);
        acc[2][0] = ffma2(a2, b01, acc[2][0]); acc[2][1] = ffma2(a2, b23, acc[2][1]);
        acc[3][0] = ffma2(a3, b01, acc[3][0]); acc[3][1] = ffma2(a3, b23, acc[3][1]);
    }
    #pragma unroll
    for (int r = 0; r < 4; r++) {
        int row = base + r0 + r;
        if (row < N) {
            float dinv = rsqrtf((float)g_deg[row]);
            float4 o;
            o.x = acc[r][0].x * dinv; o.y = acc[r][0].y * dinv;
            o.z = acc[r][1].x * dinv; o.w = acc[r][1].y * dinv;
            *(float4*)&g_hn[(size_t)row * C + c0] = o;
        }
    }
}

// 6) gather + fused BN stats: one warp per node.
__global__ void k_gather(float* __restrict__ out, int N) {
    __shared__ float ssum[64], ssq[64];
    if (threadIdx.x < 64) { ssum[threadIdx.x] = 0.f; ssq[threadIdx.x] = 0.f; }
    __syncthreads();

    int node = blockIdx.x * (blockDim.x >> 5) + (threadIdx.x >> 5);
    int lane = threadIdx.x & 31;
    float2 r = make_float2(0.f, 0.f);
    if (node < N) {
        const float2* hn2 = (const float2*)g_hn;
        int beg = g_off[node], end = g_off[node + 1];
        float2 acc = __ldg(&hn2[(size_t)node * 32 + lane]);   // self term
        for (int j0 = beg; j0 < end; j0 += 32) {
            int nj = end - j0; if (nj > 32) nj = 32;
            int sj = (lane < nj) ? __ldg(&g_srcIdx[j0 + lane]) : 0;
            int t = 0;
            for (; t + 4 <= nj; t += 4) {
                int s0 = __shfl_sync(0xffffffffu, sj, t);
                int s1 = __shfl_sync(0xffffffffu, sj, t + 1);
                int s2 = __shfl_sync(0xffffffffu, sj, t + 2);
                int s3 = __shfl_sync(0xffffffffu, sj, t + 3);
                float2 v0 = __ldg(&hn2[(size_t)s0 * 32 + lane]);
                float2 v1 = __ldg(&hn2[(size_t)s1 * 32 + lane]);
                float2 v2 = __ldg(&hn2[(size_t)s2 * 32 + lane]);
                float2 v3 = __ldg(&hn2[(size_t)s3 * 32 + lane]);
                acc = add2(acc, add2(add2(v0, v1), add2(v2, v3)));
            }
            for (; t < nj; t++) {
                int s = __shfl_sync(0xffffffffu, sj, t);
                acc = add2(acc, __ldg(&hn2[(size_t)s * 32 + lane]));
            }
        }
        float dinv = rsqrtf((float)g_deg[node]);
        r.x = acc.x * dinv; r.y = acc.y * dinv;
        ((float2*)out)[(size_t)node * 32 + lane] = r;
    }
    // per-block column partials (inactive warps contribute zeros)
    atomicAdd(&ssum[2 * lane],     r.x);
    atomicAdd(&ssum[2 * lane + 1], r.y);
    atomicAdd(&ssq[2 * lane],      r.x * r.x);
    atomicAdd(&ssq[2 * lane + 1],  r.y * r.y);
    __syncthreads();
    if (threadIdx.x < 64) {
        atomicAdd(&g_stats[threadIdx.x],      ssum[threadIdx.x]);
        atomicAdd(&g_stats[64 + threadIdx.x], ssq[threadIdx.x]);
    }
}

// 7) BN + ReLU, float4 (bias cancels exactly in training-mode BN)
__global__ void k_bn(float* __restrict__ out, const float* __restrict__ gamma,
                     const float* __restrict__ beta, int N) {
    __shared__ float scale[64], shift[64];
    if (threadIdx.x < 64) {
        float n = (float)N;
        float mean = g_stats[threadIdx.x] / n;
        float var  = g_stats[64 + threadIdx.x] / n - mean * mean;
        float sc = rsqrtf(var + 1e-5f) * gamma[threadIdx.x];
        scale[threadIdx.x] = sc;
        shift[threadIdx.x] = beta[threadIdx.x] - mean * sc;
    }
    __syncthreads();
    long long i4 = (long long)blockIdx.x * blockDim.x + threadIdx.x;
    long long tot4 = (long long)N * C / 4;
    if (i4 < tot4) {
        int c0 = (int)((i4 * 4) & 63);
        float4 v = ((const float4*)out)[i4];
        v.x = fmaxf(fmaf(v.x, scale[c0 + 0], shift[c0 + 0]), 0.f);
        v.y = fmaxf(fmaf(v.y, scale[c0 + 1], shift[c0 + 1]), 0.f);
        v.z = fmaxf(fmaf(v.z, scale[c0 + 2], shift[c0 + 2]), 0.f);
        v.w = fmaxf(fmaf(v.w, scale[c0 + 3], shift[c0 + 3]), 0.f);
        ((float4*)out)[i4] = v;
    }
}

extern "C" void kernel_launch(void* const* d_in, const int* in_sizes, int n_in,
                              void* d_out, int out_size) {
    const float* x     = (const float*)d_in[0];
    const void*  ei    = d_in[1];                 // int32 or int64; device-detected
    const float* W     = (const float*)d_in[2];
    // d_in[3] = bias (cancels exactly in training-mode BN; unused)
    const float* gamma = (const float*)d_in[4];
    const float* beta  = (const float*)d_in[5];
    float* out = (float*)d_out;

    int N = in_sizes[0] / C;
    int E = in_sizes[1] / 2;
    int nb = (N + 1023) / 1024;
    int eq = (E + 3) / 4;

    k_init<<<(N + 255) / 256, 256>>>((const int*)ei, N);
    k_deg<<<(eq + 255) / 256, 256>>>(ei, E, N);
    k_scanA<<<nb, 1024>>>(N);
    k_scanC<<<(N + 255) / 256, 256>>>(N, E, nb);
    k_bucket<<<(eq + 255) / 256, 256>>>(ei, E, N);
    k_h<<<(N + 63) / 64, 256>>>(x, W, N);
    k_gather<<<(N + 7) / 8, 256>>>(out, N);
    long long tot4 = (long long)N * C / 4;
    k_bn<<<(unsigned)((tot4 + 255) / 256), 256>>>(out, gamma, beta, N);
}

// round 12
// speedup vs baseline: 1.4006x; 1.0656x over previous
#include <cuda_runtime.h>
#include <cuda_bf16.h>
#include <cuda_fp16.h>
#include <stdint.h>

#define MAXN 100000
#define MAXE 1700000
#define C 64

__device__ int    g_is64;
__device__ int    g_deg[MAXN];                 // 1 + in-degree
__device__ int    g_off[MAXN + 1];             // CSR offsets (in-edges only)
__device__ int    g_pos[MAXN];                 // bucket cursors
__device__ int    g_blksum[128];
__device__ int    g_srcIdx[MAXE];              // sources grouped by dst
__device__ __half g_hn[(size_t)MAXN * C];      // fp16: hn[i][c] = (x@W)[i][c]*dinv[i]
__device__ float  g_stats[2 * C];

// packed f32x2 helpers (sm_100+)
__device__ __forceinline__ float2 add2(float2 a, float2 b) {
    float2 r;
    asm("add.rn.f32x2 %0, %1, %2;"
        : "=l"(reinterpret_cast<unsigned long long&>(r))
        : "l"(reinterpret_cast<unsigned long long&>(a)),
          "l"(reinterpret_cast<unsigned long long&>(b)));
    return r;
}
__device__ __forceinline__ float2 ffma2(float2 a, float2 b, float2 c) {
    float2 r;
    asm("fma.rn.f32x2 %0, %1, %2, %3;"
        : "=l"(reinterpret_cast<unsigned long long&>(r))
        : "l"(reinterpret_cast<unsigned long long&>(a)),
          "l"(reinterpret_cast<unsigned long long&>(b)),
          "l"(reinterpret_cast<unsigned long long&>(c)));
    return r;
}
__device__ __forceinline__ float2 bcast2(float a) {
    float2 r;
    asm("mov.b64 %0, {%1, %1};"
        : "=l"(reinterpret_cast<unsigned long long&>(r)) : "f"(a));
    return r;
}

__device__ __forceinline__ int edge_at(const void* ei, long long idx) {
    if (g_is64) return (int)((const long long*)ei)[idx];
    return ((const int*)ei)[idx];
}

// 1) init deg/stats + dtype detection (block 0)
__global__ void k_init(const int* __restrict__ ei32, int N) {
    int i = blockIdx.x * blockDim.x + threadIdx.x;
    if (i < N) g_deg[i] = 1;
    if (i < 2 * C) g_stats[i] = 0.f;
    if (blockIdx.x == 0) {
        __shared__ int any;
        if (threadIdx.x == 0) any = 0;
        __syncthreads();
        if (ei32[2 * threadIdx.x + 1] != 0) any = 1;  // benign race
        __syncthreads();
        if (threadIdx.x == 0) g_is64 = (any == 0) ? 1 : 0;
    }
}

// 2) in-degree count (4 edges/thread, int4 fast path)
__global__ void k_deg(const void* __restrict__ ei, int E, int N) {
    int e0 = (blockIdx.x * blockDim.x + threadIdx.x) * 4;
    if (e0 >= E) return;
    if (!g_is64 && e0 + 4 <= E) {
        int4 d4 = *(const int4*)((const int*)ei + E + e0);
        if ((unsigned)d4.x < (unsigned)N) atomicAdd(&g_deg[d4.x], 1);
        if ((unsigned)d4.y < (unsigned)N) atomicAdd(&g_deg[d4.y], 1);
        if ((unsigned)d4.z < (unsigned)N) atomicAdd(&g_deg[d4.z], 1);
        if ((unsigned)d4.w < (unsigned)N) atomicAdd(&g_deg[d4.w], 1);
    } else {
        int eend = e0 + 4 < E ? e0 + 4 : E;
        for (int e = e0; e < eend; e++) {
            int d = edge_at(ei, (long long)E + e);
            if ((unsigned)d < (unsigned)N) atomicAdd(&g_deg[d], 1);
        }
    }
}

// 3a) per-block exclusive scan of (deg-1)
__global__ void k_scanA(int N) {
    int i = blockIdx.x * 1024 + threadIdx.x;
    int v = (i < N) ? (g_deg[i] - 1) : 0;
    __shared__ int warpsum[32];
    int x = v;
    #pragma unroll
    for (int o = 1; o < 32; o <<= 1) {
        int y = __shfl_up_sync(0xffffffffu, x, o);
        if ((threadIdx.x & 31) >= o) x += y;
    }
    if ((threadIdx.x & 31) == 31) warpsum[threadIdx.x >> 5] = x;
    __syncthreads();
    if (threadIdx.x < 32) {
        int y = warpsum[threadIdx.x];
        #pragma unroll
        for (int o = 1; o < 32; o <<= 1) {
            int z = __shfl_up_sync(0xffffffffu, y, o);
            if (threadIdx.x >= o) y += z;
        }
        warpsum[threadIdx.x] = y;
    }
    __syncthreads();
    int incl = x + ((threadIdx.x >= 32) ? warpsum[(threadIdx.x >> 5) - 1] : 0);
    if (i < N) g_off[i] = incl - v;
    if (threadIdx.x == 1023) g_blksum[blockIdx.x] = incl;
}

// 3b) add block offsets (block-sum scan redone per block); init cursors
__global__ void k_scanC(int N, int E, int nb) {
    __shared__ int boff[128];
    if (threadIdx.x < 32) {
        int lane = threadIdx.x;
        int carry = 0;
        for (int base = 0; base < nb; base += 32) {
            int v = (base + lane < nb) ? g_blksum[base + lane] : 0;
            int x = v;
            #pragma unroll
            for (int o = 1; o < 32; o <<= 1) {
                int y = __shfl_up_sync(0xffffffffu, x, o);
                if (lane >= o) x += y;
            }
            if (base + lane < nb) boff[base + lane] = carry + x - v;
            carry += __shfl_sync(0xffffffffu, x, 31);
        }
    }
    __syncthreads();
    int i = blockIdx.x * blockDim.x + threadIdx.x;
    if (i < N) {
        int o = g_off[i] + boff[i >> 10];
        g_off[i] = o;
        g_pos[i] = o;
    }
    if (i == 0) g_off[N] = E;
}

// 4) bucket edges by dst (4 edges/thread, int4 fast path)
__global__ void k_bucket(const void* __restrict__ ei, int E, int N) {
    int e0 = (blockIdx.x * blockDim.x + threadIdx.x) * 4;
    if (e0 >= E) return;
    if (!g_is64 && e0 + 4 <= E) {
        const int* p = (const int*)ei;
        int4 s4 = *(const int4*)(p + e0);
        int4 d4 = *(const int4*)(p + E + e0);
        if ((unsigned)d4.x < (unsigned)N && (unsigned)s4.x < (unsigned)N)
            g_srcIdx[atomicAdd(&g_pos[d4.x], 1)] = s4.x;
        if ((unsigned)d4.y < (unsigned)N && (unsigned)s4.y < (unsigned)N)
            g_srcIdx[atomicAdd(&g_pos[d4.y], 1)] = s4.y;
        if ((unsigned)d4.z < (unsigned)N && (unsigned)s4.z < (unsigned)N)
            g_srcIdx[atomicAdd(&g_pos[d4.z], 1)] = s4.z;
        if ((unsigned)d4.w < (unsigned)N && (unsigned)s4.w < (unsigned)N)
            g_srcIdx[atomicAdd(&g_pos[d4.w], 1)] = s4.w;
    } else {
        int eend = e0 + 4 < E ? e0 + 4 : E;
        for (int e = e0; e < eend; e++) {
            int s = edge_at(ei, e);
            int d = edge_at(ei, (long long)E + e);
            if ((unsigned)d < (unsigned)N && (unsigned)s < (unsigned)N)
                g_srcIdx[atomicAdd(&g_pos[d], 1)] = s;
        }
    }
}

// 5) h = x @ W, scaled by dinv[row], stored fp16. Register-tiled, FFMA2.
__global__ void k_h(const float* __restrict__ x, const float* __restrict__ W,
                    int N) {
    __shared__ float Wsm[64 * 64];
    __shared__ float Xt[64 * 68];
    int tid = threadIdx.x;
    int base = blockIdx.x * 64;
    {
        const float4* w4 = (const float4*)W;
        float4* s4 = (float4*)Wsm;
        for (int i = tid; i < 64 * 16; i += 256) s4[i] = w4[i];
    }
    for (int s = tid; s < 1024; s += 256) {
        int row = s >> 4;
        int c0 = (s & 15) * 4;
        int gr = base + row;
        float4 v = (gr < N) ? *(const float4*)&x[(size_t)gr * C + c0]
                            : make_float4(0.f, 0.f, 0.f, 0.f);
        Xt[(c0 + 0) * 68 + row] = v.x;
        Xt[(c0 + 1) * 68 + row] = v.y;
        Xt[(c0 + 2) * 68 + row] = v.z;
        Xt[(c0 + 3) * 68 + row] = v.w;
    }
    __syncthreads();

    int tx = tid & 15, ty = tid >> 4;
    int c0 = tx * 4, r0 = ty * 4;
    float2 acc[4][2];
    #pragma unroll
    for (int r = 0; r < 4; r++) { acc[r][0] = make_float2(0.f, 0.f);
                                  acc[r][1] = make_float2(0.f, 0.f); }
    #pragma unroll 8
    for (int k = 0; k < 64; k++) {
        float4 wb = *(const float4*)&Wsm[k * 64 + c0];
        float4 xa = *(const float4*)&Xt[k * 68 + r0];
        float2 b01 = make_float2(wb.x, wb.y);
        float2 b23 = make_float2(wb.z, wb.w);
        float2 a0 = bcast2(xa.x), a1 = bcast2(xa.y);
        float2 a2 = bcast2(xa.z), a3 = bcast2(xa.w);
        acc[0][0] = ffma2(a0, b01, acc[0][0]); acc[0][1] = ffma2(a0, b23, acc[0][1]);
        acc[1][0] = ffma2(a1, b01, acc[1][0]); acc[1][1] = ffma2(a1, b23, acc[1][1]);
        acc[2][0] = ffma2(a2, b01, acc[2][0]); acc[2][1] = ffma2(a2, b23, acc[2][1]);
        acc[3][0] = ffma2(a3, b01, acc[3][0]); acc[3][1] = ffma2(a3, b23, acc[3][1]);
    }
    #pragma unroll
    for (int r = 0; r < 4; r++) {
        int row = base + r0 + r;
        if (row < N) {
            float dinv = rsqrtf((float)g_deg[row]);
            __half2 h0 = __floats2half2_rn(acc[r][0].x * dinv, acc[r][0].y * dinv);
            __half2 h1 = __floats2half2_rn(acc[r][1].x * dinv, acc[r][1].y * dinv);
            uint2 pk; pk.x = *(unsigned*)&h0; pk.y = *(unsigned*)&h1;
            *(uint2*)&g_hn[(size_t)row * C + c0] = pk;   // 8B aligned (c0 % 4 == 0)
        }
    }
}

// 6) gather (fp16 rows, fp32 accum) + fused BN stats: one warp per node.
__global__ void k_gather(float* __restrict__ out, int N) {
    __shared__ float ssum[64], ssq[64];
    if (threadIdx.x < 64) { ssum[threadIdx.x] = 0.f; ssq[threadIdx.x] = 0.f; }
    __syncthreads();

    int node = blockIdx.x * (blockDim.x >> 5) + (threadIdx.x >> 5);
    int lane = threadIdx.x & 31;
    float2 r = make_float2(0.f, 0.f);
    if (node < N) {
        const __half2* hn2 = (const __half2*)g_hn;   // 32 half2 per row
        int beg = g_off[node], end = g_off[node + 1];
        float2 acc = __half22float2(__ldg(&hn2[(size_t)node * 32 + lane])); // self
        for (int j0 = beg; j0 < end; j0 += 32) {
            int nj = end - j0; if (nj > 32) nj = 32;
            int sj = (lane < nj) ? __ldg(&g_srcIdx[j0 + lane]) : 0;
            int t = 0;
            for (; t + 4 <= nj; t += 4) {
                int s0 = __shfl_sync(0xffffffffu, sj, t);
                int s1 = __shfl_sync(0xffffffffu, sj, t + 1);
                int s2 = __shfl_sync(0xffffffffu, sj, t + 2);
                int s3 = __shfl_sync(0xffffffffu, sj, t + 3);
                float2 v0 = __half22float2(__ldg(&hn2[(size_t)s0 * 32 + lane]));
                float2 v1 = __half22float2(__ldg(&hn2[(size_t)s1 * 32 + lane]));
                float2 v2 = __half22float2(__ldg(&hn2[(size_t)s2 * 32 + lane]));
                float2 v3 = __half22float2(__ldg(&hn2[(size_t)s3 * 32 + lane]));
                acc = add2(acc, add2(add2(v0, v1), add2(v2, v3)));
            }
            for (; t < nj; t++) {
                int s = __shfl_sync(0xffffffffu, sj, t);
                acc = add2(acc, __half22float2(__ldg(&hn2[(size_t)s * 32 + lane])));
            }
        }
        float dinv = rsqrtf((float)g_deg[node]);
        r.x = acc.x * dinv; r.y = acc.y * dinv;
        ((float2*)out)[(size_t)node * 32 + lane] = r;
    }
    atomicAdd(&ssum[2 * lane],     r.x);
    atomicAdd(&ssum[2 * lane + 1], r.y);
    atomicAdd(&ssq[2 * lane],      r.x * r.x);
    atomicAdd(&ssq[2 * lane + 1],  r.y * r.y);
    __syncthreads();
    if (threadIdx.x < 64) {
        atomicAdd(&g_stats[threadIdx.x],      ssum[threadIdx.x]);
        atomicAdd(&g_stats[64 + threadIdx.x], ssq[threadIdx.x]);
    }
}

// 7) BN + ReLU, float4 (bias cancels exactly in training-mode BN)
__global__ void k_bn(float* __restrict__ out, const float* __restrict__ gamma,
                     const float* __restrict__ beta, int N) {
    __shared__ float scale[64], shift[64];
    if (threadIdx.x < 64) {
        float n = (float)N;
        float mean = g_stats[threadIdx.x] / n;
        float var  = g_stats[64 + threadIdx.x] / n - mean * mean;
        float sc = rsqrtf(var + 1e-5f) * gamma[threadIdx.x];
        scale[threadIdx.x] = sc;
        shift[threadIdx.x] = beta[threadIdx.x] - mean * sc;
    }
    __syncthreads();
    long long i4 = (long long)blockIdx.x * blockDim.x + threadIdx.x;
    long long tot4 = (long long)N * C / 4;
    if (i4 < tot4) {
        int c0 = (int)((i4 * 4) & 63);
        float4 v = ((const float4*)out)[i4];
        v.x = fmaxf(fmaf(v.x, scale[c0 + 0], shift[c0 + 0]), 0.f);
        v.y = fmaxf(fmaf(v.y, scale[c0 + 1], shift[c0 + 1]), 0.f);
        v.z = fmaxf(fmaf(v.z, scale[c0 + 2], shift[c0 + 2]), 0.f);
        v.w = fmaxf(fmaf(v.w, scale[c0 + 3], shift[c0 + 3]), 0.f);
        ((float4*)out)[i4] = v;
    }
}

extern "C" void kernel_launch(void* const* d_in, const int* in_sizes, int n_in,
                              void* d_out, int out_size) {
    const float* x     = (const float*)d_in[0];
    const void*  ei    = d_in[1];                 // int32 or int64; device-detected
    const float* W     = (const float*)d_in[2];
    // d_in[3] = bias (cancels exactly in training-mode BN; unused)
    const float* gamma = (const float*)d_in[4];
    const float* beta  = (const float*)d_in[5];
    float* out = (float*)d_out;

    int N = in_sizes[0] / C;
    int E = in_sizes[1] / 2;
    int nb = (N + 1023) / 1024;
    int eq = (E + 3) / 4;

    k_init<<<(N + 255) / 256, 256>>>((const int*)ei, N);
    k_deg<<<(eq + 255) / 256, 256>>>(ei, E, N);
    k_scanA<<<nb, 1024>>>(N);
    k_scanC<<<(N + 255) / 256, 256>>>(N, E, nb);
    k_bucket<<<(eq + 255) / 256, 256>>>(ei, E, N);
    k_h<<<(N + 63) / 64, 256>>>(x, W, N);
    k_gather<<<(N + 7) / 8, 256>>>(out, N);
    long long tot4 = (long long)N * C / 4;
    k_bn<<<(unsigned)((tot4 + 255) / 256), 256>>>(out, gamma, beta, N);
}